// round 11
// baseline (speedup 1.0000x reference)
#include <cuda_runtime.h>
#include <math.h>

// Problem dims
#define B_DIM 32
#define F_DIM 1024
#define NG    25
#define NFRM  (B_DIM * F_DIM)

// Scratch for gli (B,F,25) — static __device__ array (allocation-free per harness rules)
__device__ float g_gli[NFRM * NG];

// Segment tables (16 segments across 5 paths)
// paths: [2,5,8,11], [1,4,7,10], [3,6,9,12,15], [14,17,19,21], [13,16,18,20]
__constant__ unsigned char c_ss[16]   = {2,5,8, 1,4,7, 3,6,9,12, 14,17,19, 13,16,18};
__constant__ unsigned char c_se[16]   = {5,8,11, 4,7,10, 6,9,12,15, 17,19,21, 16,18,20};
__constant__ unsigned char c_base[5]  = {0,3,6,10,13};
__constant__ unsigned char c_cnt[5]   = {3,3,4,3,3};

// Branch-free asin, A&S 4.4.46 (abs err <= 2e-8), MUFU-only sqrt:
// asin(x) = sign(x) * ( pi/2 - sqrt(1-|x|) * poly7(|x|) )
__device__ __forceinline__ float fast_asin(float v) {
    float x = fabsf(v);
    float p = fmaf(x, -0.0012624911f,  0.0066700901f);
    p = fmaf(p, x, -0.0170881256f);
    p = fmaf(p, x,  0.0308918810f);
    p = fmaf(p, x, -0.0501743046f);
    p = fmaf(p, x,  0.0889789874f);
    p = fmaf(p, x, -0.2145988016f);
    p = fmaf(p, x,  1.5707963050f);
    float y = 1.0f - x;                 // >= 1e-7 after clip below
    float s = y * rsqrtf(y);            // sqrt(y) via MUFU.RSQ, no IEEE slow path
    float r = fmaf(-s, p, 1.57079632679f);
    return copysignf(r, v);
}

// asin( clip( d / sqrt(qa*qb) ) ), zero-norm -> 0 (matches reference where())
__device__ __forceinline__ float edge_term(float d, float qa, float qb) {
    float p = qa * qb;
    float r = rsqrtf(p);
    float v = (p > 0.f) ? d * r : 0.f;
    v = fminf(fmaxf(v, -1.f + 1e-7f), 1.f - 1e-7f);
    return fast_asin(v);
}

__device__ __forceinline__ float dot3(float4 a, float4 b) {
    return a.x * b.x + a.y * b.y + a.z * b.z;
}

__global__ __launch_bounds__(256)
void gli_kernel(const float* __restrict__ m1, const float* __restrict__ m2)
{
    __shared__ float  J1[66];        // 22 joints x 3, motion1, this frame
    __shared__ float  J2[66];
    __shared__ float4 N1[22 * 16];   // n1(a,j)=cross(s2_j-a, e2_j-a); .w=|n|^2; [a*16+j]
    __shared__ float4 N2[16 * 22];   // n2(c,i)=cross(s1_i-c, e1_i-c); .w=|n|^2; [i*22+c]
    __shared__ float3 R12[16];       // e1_i - s1_i
    __shared__ float3 R34[16];       // e2_j - s2_j
    __shared__ float  gall[256];
    __shared__ unsigned char ss[16], se[16];

    const int t  = threadIdx.x;
    const int bf = blockIdx.x;       // frame index b*F + f

    if (t < 66)        J1[t]      = m1[bf * 66 + t];
    else if (t < 132)  J2[t - 66] = m2[bf * 66 + (t - 66)];
    if (t < 16) { ss[t] = c_ss[t]; se[t] = c_se[t]; }
    __syncthreads();

    // ---- precompute shared face-normal tables (352 entries each) ----
    for (int k = t; k < 352; k += 256) {
        // N1 entry: a = joint of motion1, j = segment of motion2
        {
            int a = k >> 4, j = k & 15;
            int sj = 3 * (int)ss[j], ej = 3 * (int)se[j];
            float ax = J1[3*a], ay = J1[3*a+1], az = J1[3*a+2];
            float ux = J2[sj]   - ax, uy = J2[sj+1] - ay, uz = J2[sj+2] - az;
            float vx = J2[ej]   - ax, vy = J2[ej+1] - ay, vz = J2[ej+2] - az;
            float nx = uy*vz - uz*vy;
            float ny = uz*vx - ux*vz;
            float nz = ux*vy - uy*vx;
            N1[k] = make_float4(nx, ny, nz, nx*nx + ny*ny + nz*nz);
        }
        // N2 entry: i = segment of motion1, c = joint of motion2
        {
            int i = k / 22, c = k - 22 * i;
            int si = 3 * (int)ss[i], ei = 3 * (int)se[i];
            float cx = J2[3*c], cy = J2[3*c+1], cz = J2[3*c+2];
            float ux = J1[si]   - cx, uy = J1[si+1] - cy, uz = J1[si+2] - cz;
            float vx = J1[ei]   - cx, vy = J1[ei+1] - cy, vz = J1[ei+2] - cz;
            float nx = uy*vz - uz*vy;
            float ny = uz*vx - ux*vz;
            float nz = ux*vy - uy*vx;
            N2[k] = make_float4(nx, ny, nz, nx*nx + ny*ny + nz*nz);
        }
    }
    if (t < 16) {
        int si = 3 * (int)ss[t], ei = 3 * (int)se[t];
        R12[t] = make_float3(J1[ei] - J1[si], J1[ei+1] - J1[si+1], J1[ei+2] - J1[si+2]);
        R34[t] = make_float3(J2[ei] - J2[si], J2[ei+1] - J2[si+1], J2[ei+2] - J2[si+2]);
    }
    __syncthreads();

    // ---- per-pair Gauss integral from shared normals ----
    const int i = t >> 4;            // motion1 segment
    const int j = t & 15;            // motion2 segment

    float4 n1s = N1[(int)ss[i] * 16 + j];   // f0 =  n1s
    float4 n1e = N1[(int)se[i] * 16 + j];   // f2 = -n1e
    float4 n2s = N2[i * 22 + (int)ss[j]];   // f3 = -n2s
    float4 n2e = N2[i * 22 + (int)se[j]];   // f1 =  n2e

    float g = edge_term(dot3(n1s, n2e), n1s.w, n2e.w)    // asin(c01)
            - edge_term(dot3(n2e, n1e), n2e.w, n1e.w)    // asin(c12)
            + edge_term(dot3(n1e, n2s), n1e.w, n2s.w)    // asin(c23)
            - edge_term(dot3(n2s, n1s), n2s.w, n1s.w);   // asin(c30)

    // sign = dot(cross(r34, r12), r13),  r13 = s2_j - s1_i
    float3 a = R34[j], b = R12[i];
    float cx = a.y*b.z - a.z*b.y;
    float cy = a.z*b.x - a.x*b.z;
    float cz = a.x*b.y - a.y*b.x;
    int sj = 3 * (int)ss[j], si = 3 * (int)ss[i];
    float sgn = cx * (J2[sj]   - J1[si])
              + cy * (J2[sj+1] - J1[si+1])
              + cz * (J2[sj+2] - J1[si+2]);
    g = (sgn <= 0.f) ? -g : g;
    gall[t] = g * 0.07957747154594767f;   // 1/(4*pi)
    __syncthreads();

    // Deterministic fixed-order reduction into the 25 path-pair channels.
    if (t < NG) {
        const int pa = t / 5;
        const int pb = t - 5 * pa;
        const int i0 = c_base[pa], na = c_cnt[pa];
        const int j0 = c_base[pb], nb = c_cnt[pb];
        float s = 0.f;
        for (int u = 0; u < na; u++)
            for (int v = 0; v < nb; v++)
                s += gall[(i0 + u) * 16 + (j0 + v)];
        g_gli[bf * NG + t] = s;
    }
}

// Simple per-thread velocity kernel (R8 version: 5.9us, latency-bound but small)
__global__ void vel_kernel(float* __restrict__ out)
{
    const int n = B_DIM * (F_DIM - 1);
    int idx = blockIdx.x * blockDim.x + threadIdx.x;
    if (idx >= n) return;
    int b = idx / (F_DIM - 1);
    int f = idx - b * (F_DIM - 1);
    const float* g0 = g_gli + ((long)b * F_DIM + f) * NG;
    float m = 0.f;
#pragma unroll
    for (int c = 0; c < NG; c++)
        m = fmaxf(m, fabsf(g0[NG + c] - g0[c]));
    out[idx] = m;
}

extern "C" void kernel_launch(void* const* d_in, const int* in_sizes, int n_in,
                              void* d_out, int out_size)
{
    const float* m1 = (const float*)d_in[0];   // motion1 (32,1024,22,3) f32
    const float* m2 = (const float*)d_in[1];   // motion2 (32,1024,22,3) f32
    float* out = (float*)d_out;                // (32,1023) f32

    gli_kernel<<<NFRM, 256>>>(m1, m2);

    const int n = B_DIM * (F_DIM - 1);
    vel_kernel<<<(n + 255) / 256, 256>>>(out);
}

// round 12
// speedup vs baseline: 1.3482x; 1.3482x over previous
#include <cuda_runtime.h>
#include <math.h>

// Problem dims
#define B_DIM 32
#define F_DIM 1024
#define NG    25
#define NFRM  (B_DIM * F_DIM)

// Scratch for gli (B,F,25) — static __device__ array (allocation-free per harness rules)
__device__ float g_gli[NFRM * NG];

// Segment tables (16 segments across 5 paths)
// paths: [2,5,8,11], [1,4,7,10], [3,6,9,12,15], [14,17,19,21], [13,16,18,20]
__constant__ unsigned char c_ss[16]   = {2,5,8, 1,4,7, 3,6,9,12, 14,17,19, 13,16,18};
__constant__ unsigned char c_se[16]   = {5,8,11, 4,7,10, 6,9,12,15, 17,19,21, 16,18,20};
__constant__ unsigned char c_base[5]  = {0,3,6,10,13};
__constant__ unsigned char c_cnt[5]   = {3,3,4,3,3};

// Branch-free asin, A&S 4.4.46 (abs err <= 2e-8), MUFU-only sqrt:
// asin(x) = sign(x) * ( pi/2 - sqrt(1-|x|) * poly7(|x|) )
__device__ __forceinline__ float fast_asin(float v) {
    float x = fabsf(v);
    float p = fmaf(x, -0.0012624911f,  0.0066700901f);
    p = fmaf(p, x, -0.0170881256f);
    p = fmaf(p, x,  0.0308918810f);
    p = fmaf(p, x, -0.0501743046f);
    p = fmaf(p, x,  0.0889789874f);
    p = fmaf(p, x, -0.2145988016f);
    p = fmaf(p, x,  1.5707963050f);
    float y = 1.0f - x;                 // >= 1e-7 after clip
    float s = y * rsqrtf(y);            // sqrt(y) via MUFU.RSQ, no IEEE slow path
    float r = fmaf(-s, p, 1.57079632679f);
    return copysignf(r, v);
}

// asin( clip( d / sqrt(qa*qb) ) ), zero-norm -> 0 (matches reference where())
__device__ __forceinline__ float edge_term(float d, float qa, float qb) {
    float p = qa * qb;
    float r = rsqrtf(p);
    float v = (p > 0.f) ? d * r : 0.f;
    v = fminf(fmaxf(v, -1.f + 1e-7f), 1.f - 1e-7f);
    return fast_asin(v);
}

__global__ __launch_bounds__(256)
void gli_kernel(const float* __restrict__ m1, const float* __restrict__ m2)
{
    __shared__ float4 J1v[22];        // motion1 joints, float4-padded
    __shared__ float4 J2v[22];        // motion2 joints
    __shared__ float4 R12[16];        // e1_i - s1_i per segment
    __shared__ float4 R34[16];        // e2_j - s2_j per segment
    __shared__ float  gall[256];
    __shared__ unsigned char ss[16];

    const int t  = threadIdx.x;
    const int bf = blockIdx.x;        // frame index b*F + f
    const float* base1 = m1 + bf * 66;
    const float* base2 = m2 + bf * 66;

    // Load phase: warps 0/1 pack joints; warps 2/3 build segment-direction
    // tables straight from gmem (no dependence on warps 0/1) -> ONE barrier.
    if (t < 22) {
        J1v[t] = make_float4(base1[3*t], base1[3*t+1], base1[3*t+2], 0.f);
    } else if (t >= 32 && t < 54) {
        int a = t - 32;
        J2v[a] = make_float4(base2[3*a], base2[3*a+1], base2[3*a+2], 0.f);
    } else if (t >= 64 && t < 80) {
        int i = t - 64;
        int s = 3 * (int)c_ss[i], e = 3 * (int)c_se[i];
        R12[i] = make_float4(base1[e]-base1[s], base1[e+1]-base1[s+1],
                             base1[e+2]-base1[s+2], 0.f);
    } else if (t >= 96 && t < 112) {
        int j = t - 96;
        int s = 3 * (int)c_ss[j], e = 3 * (int)c_se[j];
        R34[j] = make_float4(base2[e]-base2[s], base2[e+1]-base2[s+1],
                             base2[e+2]-base2[s+2], 0.f);
    }
    if (t < 16) ss[t] = c_ss[t];
    __syncthreads();

    // ---- per-pair Gauss integral, 3-cross factorization ----
    // P = r13 x r34, Q = r12 x r13, R = r12 x r34
    // f0 = P, f1 = Q+R, f2 = R-P, f3 = -Q, sign = -(R . r13)
    const int i = t >> 4;             // motion1 segment
    const int j = t & 15;             // motion2 segment

    float4 p1 = J1v[ss[i]];           // s1
    float4 p2 = J2v[ss[j]];           // s2
    float4 A  = R12[i];               // r12
    float4 B  = R34[j];               // r34

    float rx = p2.x - p1.x, ry = p2.y - p1.y, rz = p2.z - p1.z;   // r13

    float Px = ry*B.z - rz*B.y, Py = rz*B.x - rx*B.z, Pz = rx*B.y - ry*B.x;
    float Qx = A.y*rz - A.z*ry, Qy = A.z*rx - A.x*rz, Qz = A.x*ry - A.y*rx;
    float Rx = A.y*B.z - A.z*B.y, Ry = A.z*B.x - A.x*B.z, Rz = A.x*B.y - A.y*B.x;

    float f1x = Qx + Rx, f1y = Qy + Ry, f1z = Qz + Rz;   // f1
    float f2x = Rx - Px, f2y = Ry - Py, f2z = Rz - Pz;   // f2

    float q0 = Px*Px + Py*Py + Pz*Pz;
    float q1 = f1x*f1x + f1y*f1y + f1z*f1z;
    float q2 = f2x*f2x + f2y*f2y + f2z*f2z;
    float q3 = Qx*Qx + Qy*Qy + Qz*Qz;

    float d01 = Px*f1x + Py*f1y + Pz*f1z;                // f0.f1
    float d12 = f1x*f2x + f1y*f2y + f1z*f2z;             // f1.f2
    float d23 = f2x*Qx + f2y*Qy + f2z*Qz;                // -(f2.f3)
    float d30 = Px*Qx + Py*Qy + Pz*Qz;                   // -(f3.f0)

    float g = edge_term(d01, q0, q1)
            + edge_term(d12, q1, q2)
            - edge_term(d23, q2, q3)
            - edge_term(d30, q3, q0);

    float sgn = -(Rx*rx + Ry*ry + Rz*rz);                // dot(cross(r34,r12), r13)
    g = (sgn <= 0.f) ? -g : g;
    gall[t] = g * 0.07957747154594767f;                  // 1/(4*pi)
    __syncthreads();

    // Deterministic fixed-order reduction into the 25 path-pair channels.
    if (t < NG) {
        const int pa = t / 5;
        const int pb = t - 5 * pa;
        const int i0 = c_base[pa], na = c_cnt[pa];
        const int j0 = c_base[pb], nb = c_cnt[pb];
        float s = 0.f;
        for (int u = 0; u < na; u++)
            for (int v = 0; v < nb; v++)
                s += gall[(i0 + u) * 16 + (j0 + v)];
        g_gli[bf * NG + t] = s;
    }
}

// Velocity: 4 threads per output, butterfly max -> 4x MLP vs one-thread version.
__global__ void vel_kernel(float* __restrict__ out)
{
    const int n   = B_DIM * (F_DIM - 1);
    int gid  = blockIdx.x * blockDim.x + threadIdx.x;
    int idx  = gid >> 2;
    int lane = gid & 3;
    if (idx >= n) return;
    int b = idx / (F_DIM - 1);
    int f = idx - b * (F_DIM - 1);
    const float* g0 = g_gli + (b * F_DIM + f) * NG;
    float m = 0.f;
#pragma unroll
    for (int c = lane; c < NG; c += 4)
        m = fmaxf(m, fabsf(g0[NG + c] - g0[c]));
    m = fmaxf(m, __shfl_xor_sync(0xffffffffu, m, 1));
    m = fmaxf(m, __shfl_xor_sync(0xffffffffu, m, 2));
    if (lane == 0) out[idx] = m;
}

extern "C" void kernel_launch(void* const* d_in, const int* in_sizes, int n_in,
                              void* d_out, int out_size)
{
    const float* m1 = (const float*)d_in[0];   // motion1 (32,1024,22,3) f32
    const float* m2 = (const float*)d_in[1];   // motion2 (32,1024,22,3) f32
    float* out = (float*)d_out;                // (32,1023) f32

    gli_kernel<<<NFRM, 256>>>(m1, m2);

    const int nthreads = B_DIM * (F_DIM - 1) * 4;
    vel_kernel<<<(nthreads + 255) / 256, 256>>>(out);
}

// round 13
// speedup vs baseline: 1.5089x; 1.1192x over previous
#include <cuda_runtime.h>
#include <math.h>

// Problem dims
#define B_DIM 32
#define F_DIM 1024
#define NG    25
#define NFRM  (B_DIM * F_DIM)
#define FPC   2                       // frames per CTA

// gli scratch, CHANNEL-MAJOR: g_gli[c * NFRM + bf]  (coalesced vel reads)
__device__ float g_gli[NG * NFRM];

// Segment tables (16 segments across 5 paths)
// paths: [2,5,8,11], [1,4,7,10], [3,6,9,12,15], [14,17,19,21], [13,16,18,20]
__constant__ unsigned char c_ss[16]   = {2,5,8, 1,4,7, 3,6,9,12, 14,17,19, 13,16,18};
__constant__ unsigned char c_se[16]   = {5,8,11, 4,7,10, 6,9,12,15, 17,19,21, 16,18,20};
__constant__ unsigned char c_base[5]  = {0,3,6,10,13};
__constant__ unsigned char c_cnt[5]   = {3,3,4,3,3};

// Branch-free asin, A&S 4.4.46 (abs err <= 2e-8), MUFU-only sqrt:
// asin(x) = sign(x) * ( pi/2 - sqrt(1-|x|) * poly7(|x|) )
__device__ __forceinline__ float fast_asin(float v) {
    float x = fabsf(v);
    float p = fmaf(x, -0.0012624911f,  0.0066700901f);
    p = fmaf(p, x, -0.0170881256f);
    p = fmaf(p, x,  0.0308918810f);
    p = fmaf(p, x, -0.0501743046f);
    p = fmaf(p, x,  0.0889789874f);
    p = fmaf(p, x, -0.2145988016f);
    p = fmaf(p, x,  1.5707963050f);
    float y = 1.0f - x;                 // >= 1e-7 after clip
    float s = y * rsqrtf(y);            // sqrt(y) via MUFU.RSQ, no IEEE slow path
    float r = fmaf(-s, p, 1.57079632679f);
    return copysignf(r, v);
}

// asin( clip( d / sqrt(qa*qb) ) ), zero-norm -> 0 (matches reference where())
__device__ __forceinline__ float edge_term(float d, float qa, float qb) {
    float p = qa * qb;
    float r = rsqrtf(p);
    float v = (p > 0.f) ? d * r : 0.f;
    v = fminf(fmaxf(v, -1.f + 1e-7f), 1.f - 1e-7f);
    return fast_asin(v);
}

__global__ __launch_bounds__(256)
void gli_kernel(const float* __restrict__ m1, const float* __restrict__ m2)
{
    __shared__ float4 J1v[FPC][22];     // motion1 joints, float4-padded
    __shared__ float4 J2v[FPC][22];     // motion2 joints
    __shared__ float4 R12[FPC][16];     // e1_i - s1_i per segment
    __shared__ float4 R34[FPC][16];     // e2_j - s2_j per segment
    __shared__ float  gall[FPC][256];
    __shared__ unsigned char ss[16];

    const int t   = threadIdx.x;
    const int bf0 = blockIdx.x * FPC;

    // Load phase: warps 0-3 stage frame 0, warps 4-7 stage frame 1 (one barrier).
    {
        const int ff = t >> 7;              // 0 or 1
        const int u  = t & 127;             // lane within frame-half
        const float* base1 = m1 + (bf0 + ff) * 66;
        const float* base2 = m2 + (bf0 + ff) * 66;
        if (u < 22) {
            J1v[ff][u] = make_float4(base1[3*u], base1[3*u+1], base1[3*u+2], 0.f);
        } else if (u >= 32 && u < 54) {
            int a = u - 32;
            J2v[ff][a] = make_float4(base2[3*a], base2[3*a+1], base2[3*a+2], 0.f);
        } else if (u >= 64 && u < 80) {
            int i = u - 64;
            int s = 3 * (int)c_ss[i], e = 3 * (int)c_se[i];
            R12[ff][i] = make_float4(base1[e]-base1[s], base1[e+1]-base1[s+1],
                                     base1[e+2]-base1[s+2], 0.f);
        } else if (u >= 96 && u < 112) {
            int j = u - 96;
            int s = 3 * (int)c_ss[j], e = 3 * (int)c_se[j];
            R34[ff][j] = make_float4(base2[e]-base2[s], base2[e+1]-base2[s+1],
                                     base2[e+2]-base2[s+2], 0.f);
        }
        if (t < 16) ss[t] = c_ss[t];
    }
    __syncthreads();

    // ---- per-pair Gauss integral for BOTH frames (independent chains = ILP x2) ----
    // P = r13 x r34, Q = r12 x r13, R = r12 x r34
    // f0 = P, f1 = Q+R, f2 = R-P, f3 = -Q, sign = -(R . r13)
    const int i  = t >> 4;              // motion1 segment
    const int j  = t & 15;              // motion2 segment
    const int si = (int)ss[i];
    const int sj = (int)ss[j];

#pragma unroll
    for (int ff = 0; ff < FPC; ff++) {
        float4 p1 = J1v[ff][si];        // s1
        float4 p2 = J2v[ff][sj];        // s2
        float4 A  = R12[ff][i];         // r12
        float4 B  = R34[ff][j];         // r34

        float rx = p2.x - p1.x, ry = p2.y - p1.y, rz = p2.z - p1.z;   // r13

        float Px = ry*B.z - rz*B.y, Py = rz*B.x - rx*B.z, Pz = rx*B.y - ry*B.x;
        float Qx = A.y*rz - A.z*ry, Qy = A.z*rx - A.x*rz, Qz = A.x*ry - A.y*rx;
        float Rx = A.y*B.z - A.z*B.y, Ry = A.z*B.x - A.x*B.z, Rz = A.x*B.y - A.y*B.x;

        float f1x = Qx + Rx, f1y = Qy + Ry, f1z = Qz + Rz;   // f1
        float f2x = Rx - Px, f2y = Ry - Py, f2z = Rz - Pz;   // f2

        float q0 = Px*Px + Py*Py + Pz*Pz;
        float q1 = f1x*f1x + f1y*f1y + f1z*f1z;
        float q2 = f2x*f2x + f2y*f2y + f2z*f2z;
        float q3 = Qx*Qx + Qy*Qy + Qz*Qz;

        float d01 = Px*f1x + Py*f1y + Pz*f1z;                // f0.f1
        float d12 = f1x*f2x + f1y*f2y + f1z*f2z;             // f1.f2
        float d23 = f2x*Qx + f2y*Qy + f2z*Qz;                // -(f2.f3)
        float d30 = Px*Qx + Py*Qy + Pz*Qz;                   // -(f3.f0)

        float g = edge_term(d01, q0, q1)
                + edge_term(d12, q1, q2)
                - edge_term(d23, q2, q3)
                - edge_term(d30, q3, q0);

        float sgn = -(Rx*rx + Ry*ry + Rz*rz);                // dot(cross(r34,r12), r13)
        g = (sgn <= 0.f) ? -g : g;
        gall[ff][t] = g * 0.07957747154594767f;              // 1/(4*pi)
    }
    __syncthreads();

    // Deterministic fixed-order reduction; frame 0 in warp 0, frame 1 in warp 4.
    {
        const int ff = t >> 7;
        const int c  = t & 127;
        if (c < NG) {
            const int pa = c / 5;
            const int pb = c - 5 * pa;
            const int i0 = c_base[pa], na = c_cnt[pa];
            const int j0 = c_base[pb], nb = c_cnt[pb];
            float s = 0.f;
            for (int u = 0; u < na; u++)
                for (int v = 0; v < nb; v++)
                    s += gall[ff][(i0 + u) * 16 + (j0 + v)];
            g_gli[c * NFRM + (bf0 + ff)] = s;    // channel-major
        }
    }
}

// Velocity: channel-major gli -> fully coalesced loads; one thread per output.
__global__ __launch_bounds__(256)
void vel_kernel(float* __restrict__ out)
{
    const int n = B_DIM * (F_DIM - 1);
    int idx = blockIdx.x * blockDim.x + threadIdx.x;
    if (idx >= n) return;
    int b  = idx / (F_DIM - 1);
    int f  = idx - b * (F_DIM - 1);
    int bf = b * F_DIM + f;
    float m = 0.f;
#pragma unroll
    for (int c = 0; c < NG; c++) {
        float a0 = g_gli[c * NFRM + bf];
        float a1 = g_gli[c * NFRM + bf + 1];
        m = fmaxf(m, fabsf(a1 - a0));
    }
    out[idx] = m;
}

extern "C" void kernel_launch(void* const* d_in, const int* in_sizes, int n_in,
                              void* d_out, int out_size)
{
    const float* m1 = (const float*)d_in[0];   // motion1 (32,1024,22,3) f32
    const float* m2 = (const float*)d_in[1];   // motion2 (32,1024,22,3) f32
    float* out = (float*)d_out;                // (32,1023) f32

    gli_kernel<<<NFRM / FPC, 256>>>(m1, m2);

    const int n = B_DIM * (F_DIM - 1);
    vel_kernel<<<(n + 255) / 256, 256>>>(out);
}

// round 14
// speedup vs baseline: 1.5132x; 1.0028x over previous
#include <cuda_runtime.h>
#include <math.h>

// Problem dims
#define B_DIM 32
#define F_DIM 1024
#define NG    25
#define NFRM  (B_DIM * F_DIM)
#define FPC   2                       // frames per CTA

// gli scratch, CHANNEL-MAJOR: g_gli[c * NFRM + bf]  (coalesced vel reads)
__device__ float g_gli[NG * NFRM];

// Segment tables (16 segments across 5 paths)
// paths: [2,5,8,11], [1,4,7,10], [3,6,9,12,15], [14,17,19,21], [13,16,18,20]
__constant__ unsigned char c_ss[16]   = {2,5,8, 1,4,7, 3,6,9,12, 14,17,19, 13,16,18};
__constant__ unsigned char c_se[16]   = {5,8,11, 4,7,10, 6,9,12,15, 17,19,21, 16,18,20};
__constant__ unsigned char c_base[5]  = {0,3,6,10,13};
__constant__ unsigned char c_cnt[5]   = {3,3,4,3,3};

// Branch-free asin, A&S 4.4.46 (abs err <= 2e-8), MUFU-only sqrt:
// asin(x) = sign(x) * ( pi/2 - sqrt(1-|x|) * poly7(|x|) )
__device__ __forceinline__ float fast_asin(float v) {
    float x = fabsf(v);
    float p = fmaf(x, -0.0012624911f,  0.0066700901f);
    p = fmaf(p, x, -0.0170881256f);
    p = fmaf(p, x,  0.0308918810f);
    p = fmaf(p, x, -0.0501743046f);
    p = fmaf(p, x,  0.0889789874f);
    p = fmaf(p, x, -0.2145988016f);
    p = fmaf(p, x,  1.5707963050f);
    float y = 1.0f - x;                 // >= 1e-7 after clip
    float s = y * rsqrtf(y);            // sqrt(y) via MUFU.RSQ, no IEEE slow path
    float r = fmaf(-s, p, 1.57079632679f);
    return copysignf(r, v);
}

// asin( clip( d / sqrt(qa*qb) ) ), zero-norm -> 0 (matches reference where())
__device__ __forceinline__ float edge_term(float d, float qa, float qb) {
    float p = qa * qb;
    float r = rsqrtf(p);
    float v = (p > 0.f) ? d * r : 0.f;
    v = fminf(fmaxf(v, -1.f + 1e-7f), 1.f - 1e-7f);
    return fast_asin(v);
}

__global__ __launch_bounds__(256)
void gli_kernel(const float* __restrict__ m1, const float* __restrict__ m2)
{
    __shared__ float4 J1v[FPC][22];     // motion1 joints, float4-padded
    __shared__ float4 J2v[FPC][22];     // motion2 joints
    __shared__ float4 R12[FPC][16];     // e1_i - s1_i per segment
    __shared__ float4 R34[FPC][16];     // e2_j - s2_j per segment
    __shared__ float  gall[FPC][256];
    __shared__ unsigned char ss[16];

    const int t   = threadIdx.x;
    const int bf0 = blockIdx.x * FPC;

    // Load phase: warps 0-3 stage frame 0, warps 4-7 stage frame 1 (one barrier).
    {
        const int ff = t >> 7;              // 0 or 1
        const int u  = t & 127;             // lane within frame-half
        const float* base1 = m1 + (bf0 + ff) * 66;
        const float* base2 = m2 + (bf0 + ff) * 66;
        if (u < 22) {
            J1v[ff][u] = make_float4(base1[3*u], base1[3*u+1], base1[3*u+2], 0.f);
        } else if (u >= 32 && u < 54) {
            int a = u - 32;
            J2v[ff][a] = make_float4(base2[3*a], base2[3*a+1], base2[3*a+2], 0.f);
        } else if (u >= 64 && u < 80) {
            int i = u - 64;
            int s = 3 * (int)c_ss[i], e = 3 * (int)c_se[i];
            R12[ff][i] = make_float4(base1[e]-base1[s], base1[e+1]-base1[s+1],
                                     base1[e+2]-base1[s+2], 0.f);
        } else if (u >= 96 && u < 112) {
            int j = u - 96;
            int s = 3 * (int)c_ss[j], e = 3 * (int)c_se[j];
            R34[ff][j] = make_float4(base2[e]-base2[s], base2[e+1]-base2[s+1],
                                     base2[e+2]-base2[s+2], 0.f);
        }
        if (t < 16) ss[t] = c_ss[t];
    }
    __syncthreads();

    // ---- per-pair Gauss integral for BOTH frames (independent chains = ILP x2) ----
    // P = r13 x r34, Q = r12 x r13, R = r12 x r34
    // f0 = P, f1 = Q+R, f2 = R-P, f3 = -Q, sign = -(R . r13)
    const int i  = t >> 4;              // motion1 segment
    const int j  = t & 15;              // motion2 segment
    const int si = (int)ss[i];
    const int sj = (int)ss[j];

#pragma unroll
    for (int ff = 0; ff < FPC; ff++) {
        float4 p1 = J1v[ff][si];        // s1
        float4 p2 = J2v[ff][sj];        // s2
        float4 A  = R12[ff][i];         // r12
        float4 B  = R34[ff][j];         // r34

        float rx = p2.x - p1.x, ry = p2.y - p1.y, rz = p2.z - p1.z;   // r13

        float Px = ry*B.z - rz*B.y, Py = rz*B.x - rx*B.z, Pz = rx*B.y - ry*B.x;
        float Qx = A.y*rz - A.z*ry, Qy = A.z*rx - A.x*rz, Qz = A.x*ry - A.y*rx;
        float Rx = A.y*B.z - A.z*B.y, Ry = A.z*B.x - A.x*B.z, Rz = A.x*B.y - A.y*B.x;

        float f1x = Qx + Rx, f1y = Qy + Ry, f1z = Qz + Rz;   // f1
        float f2x = Rx - Px, f2y = Ry - Py, f2z = Rz - Pz;   // f2

        float q0 = Px*Px + Py*Py + Pz*Pz;
        float q1 = f1x*f1x + f1y*f1y + f1z*f1z;
        float q2 = f2x*f2x + f2y*f2y + f2z*f2z;
        float q3 = Qx*Qx + Qy*Qy + Qz*Qz;

        float d01 = Px*f1x + Py*f1y + Pz*f1z;                // f0.f1
        float d12 = f1x*f2x + f1y*f2y + f1z*f2z;             // f1.f2
        float d23 = f2x*Qx + f2y*Qy + f2z*Qz;                // -(f2.f3)
        float d30 = Px*Qx + Py*Qy + Pz*Qz;                   // -(f3.f0)

        float g = edge_term(d01, q0, q1)
                + edge_term(d12, q1, q2)
                - edge_term(d23, q2, q3)
                - edge_term(d30, q3, q0);

        float sgn = -(Rx*rx + Ry*ry + Rz*rz);                // dot(cross(r34,r12), r13)
        g = (sgn <= 0.f) ? -g : g;
        gall[ff][t] = g * 0.07957747154594767f;              // 1/(4*pi)
    }
    __syncthreads();

    // Deterministic fixed-order reduction; frame 0 in warp 0, frame 1 in warp 4.
    {
        const int ff = t >> 7;
        const int c  = t & 127;
        if (c < NG) {
            const int pa = c / 5;
            const int pb = c - 5 * pa;
            const int i0 = c_base[pa], na = c_cnt[pa];
            const int j0 = c_base[pb], nb = c_cnt[pb];
            float s = 0.f;
            for (int u = 0; u < na; u++)
                for (int v = 0; v < nb; v++)
                    s += gall[ff][(i0 + u) * 16 + (j0 + v)];
            g_gli[c * NFRM + (bf0 + ff)] = s;    // channel-major
        }
    }
}

// Velocity: channel-major gli -> fully coalesced loads; one thread per output.
__global__ __launch_bounds__(256)
void vel_kernel(float* __restrict__ out)
{
    const int n = B_DIM * (F_DIM - 1);
    int idx = blockIdx.x * blockDim.x + threadIdx.x;
    if (idx >= n) return;
    int b  = idx / (F_DIM - 1);
    int f  = idx - b * (F_DIM - 1);
    int bf = b * F_DIM + f;
    float m = 0.f;
#pragma unroll
    for (int c = 0; c < NG; c++) {
        float a0 = g_gli[c * NFRM + bf];
        float a1 = g_gli[c * NFRM + bf + 1];
        m = fmaxf(m, fabsf(a1 - a0));
    }
    out[idx] = m;
}

extern "C" void kernel_launch(void* const* d_in, const int* in_sizes, int n_in,
                              void* d_out, int out_size)
{
    const float* m1 = (const float*)d_in[0];   // motion1 (32,1024,22,3) f32
    const float* m2 = (const float*)d_in[1];   // motion2 (32,1024,22,3) f32
    float* out = (float*)d_out;                // (32,1023) f32

    gli_kernel<<<NFRM / FPC, 256>>>(m1, m2);

    const int n = B_DIM * (F_DIM - 1);
    vel_kernel<<<(n + 255) / 256, 256>>>(out);
}

// round 15
// speedup vs baseline: 1.5203x; 1.0047x over previous
#include <cuda_runtime.h>
#include <math.h>

// Problem dims
#define B_DIM 32
#define F_DIM 1024
#define NG    25
#define NFRM  (B_DIM * F_DIM)
#define FPC   2                       // frames per CTA

// gli scratch, CHANNEL-MAJOR: g_gli[c * NFRM + bf]  (coalesced vel reads)
__device__ float g_gli[NG * NFRM];

// Segment tables (16 segments across 5 paths)
// paths: [2,5,8,11], [1,4,7,10], [3,6,9,12,15], [14,17,19,21], [13,16,18,20]
__constant__ unsigned char c_ss[16]   = {2,5,8, 1,4,7, 3,6,9,12, 14,17,19, 13,16,18};
__constant__ unsigned char c_se[16]   = {5,8,11, 4,7,10, 6,9,12,15, 17,19,21, 16,18,20};
__constant__ unsigned char c_base[5]  = {0,3,6,10,13};
__constant__ unsigned char c_cnt[5]   = {3,3,4,3,3};

// Branch-free asin, A&S 4.4.46 (abs err <= 2e-8), MUFU-only sqrt:
// asin(x) = sign(x) * ( pi/2 - sqrt(1-|x|) * poly7(|x|) )
__device__ __forceinline__ float fast_asin(float v) {
    float x = fabsf(v);
    float p = fmaf(x, -0.0012624911f,  0.0066700901f);
    p = fmaf(p, x, -0.0170881256f);
    p = fmaf(p, x,  0.0308918810f);
    p = fmaf(p, x, -0.0501743046f);
    p = fmaf(p, x,  0.0889789874f);
    p = fmaf(p, x, -0.2145988016f);
    p = fmaf(p, x,  1.5707963050f);
    float y = 1.0f - x;                 // >= 1e-7 after clip
    float s = y * rsqrtf(y);            // sqrt(y) via MUFU.RSQ, no IEEE slow path
    float r = fmaf(-s, p, 1.57079632679f);
    return copysignf(r, v);
}

// asin( clip( d / sqrt(qa*qb) ) ), zero-norm -> 0 (matches reference where())
__device__ __forceinline__ float edge_term(float d, float qa, float qb) {
    float p = qa * qb;
    float r = rsqrtf(p);
    float v = (p > 0.f) ? d * r : 0.f;
    v = fminf(fmaxf(v, -1.f + 1e-7f), 1.f - 1e-7f);
    return fast_asin(v);
}

__global__ __launch_bounds__(256)
void gli_kernel(const float* __restrict__ m1, const float* __restrict__ m2)
{
    __shared__ float4 J1v[FPC][22];     // motion1 joints, float4-padded
    __shared__ float4 J2v[FPC][22];     // motion2 joints
    __shared__ float4 R12[FPC][16];     // e1_i - s1_i per segment
    __shared__ float4 R34[FPC][16];     // e2_j - s2_j per segment
    __shared__ float  gall[FPC][256];
    __shared__ unsigned char ss[16];

    const int t   = threadIdx.x;
    const int bf0 = blockIdx.x * FPC;

    // Load phase: warps 0-3 stage frame 0, warps 4-7 stage frame 1 (one barrier).
    {
        const int ff = t >> 7;              // 0 or 1
        const int u  = t & 127;             // lane within frame-half
        const float* base1 = m1 + (bf0 + ff) * 66;
        const float* base2 = m2 + (bf0 + ff) * 66;
        if (u < 22) {
            J1v[ff][u] = make_float4(base1[3*u], base1[3*u+1], base1[3*u+2], 0.f);
        } else if (u >= 32 && u < 54) {
            int a = u - 32;
            J2v[ff][a] = make_float4(base2[3*a], base2[3*a+1], base2[3*a+2], 0.f);
        } else if (u >= 64 && u < 80) {
            int i = u - 64;
            int s = 3 * (int)c_ss[i], e = 3 * (int)c_se[i];
            R12[ff][i] = make_float4(base1[e]-base1[s], base1[e+1]-base1[s+1],
                                     base1[e+2]-base1[s+2], 0.f);
        } else if (u >= 96 && u < 112) {
            int j = u - 96;
            int s = 3 * (int)c_ss[j], e = 3 * (int)c_se[j];
            R34[ff][j] = make_float4(base2[e]-base2[s], base2[e+1]-base2[s+1],
                                     base2[e+2]-base2[s+2], 0.f);
        }
        if (t < 16) ss[t] = c_ss[t];
    }
    __syncthreads();

    // ---- per-pair Gauss integral for BOTH frames (independent chains = ILP x2) ----
    // P = r13 x r34, Q = r12 x r13, R = r12 x r34
    // f0 = P, f1 = Q+R, f2 = R-P, f3 = -Q, sign = -(R . r13)
    const int i  = t >> 4;              // motion1 segment
    const int j  = t & 15;              // motion2 segment
    const int si = (int)ss[i];
    const int sj = (int)ss[j];

#pragma unroll
    for (int ff = 0; ff < FPC; ff++) {
        float4 p1 = J1v[ff][si];        // s1
        float4 p2 = J2v[ff][sj];        // s2
        float4 A  = R12[ff][i];         // r12
        float4 B  = R34[ff][j];         // r34

        float rx = p2.x - p1.x, ry = p2.y - p1.y, rz = p2.z - p1.z;   // r13

        float Px = ry*B.z - rz*B.y, Py = rz*B.x - rx*B.z, Pz = rx*B.y - ry*B.x;
        float Qx = A.y*rz - A.z*ry, Qy = A.z*rx - A.x*rz, Qz = A.x*ry - A.y*rx;
        float Rx = A.y*B.z - A.z*B.y, Ry = A.z*B.x - A.x*B.z, Rz = A.x*B.y - A.y*B.x;

        float f1x = Qx + Rx, f1y = Qy + Ry, f1z = Qz + Rz;   // f1
        float f2x = Rx - Px, f2y = Ry - Py, f2z = Rz - Pz;   // f2

        float q0 = Px*Px + Py*Py + Pz*Pz;
        float q1 = f1x*f1x + f1y*f1y + f1z*f1z;
        float q2 = f2x*f2x + f2y*f2y + f2z*f2z;
        float q3 = Qx*Qx + Qy*Qy + Qz*Qz;

        float d01 = Px*f1x + Py*f1y + Pz*f1z;                // f0.f1
        float d12 = f1x*f2x + f1y*f2y + f1z*f2z;             // f1.f2
        float d23 = f2x*Qx + f2y*Qy + f2z*Qz;                // -(f2.f3)
        float d30 = Px*Qx + Py*Qy + Pz*Qz;                   // -(f3.f0)

        float g = edge_term(d01, q0, q1)
                + edge_term(d12, q1, q2)
                - edge_term(d23, q2, q3)
                - edge_term(d30, q3, q0);

        float sgn = -(Rx*rx + Ry*ry + Rz*rz);                // dot(cross(r34,r12), r13)
        g = (sgn <= 0.f) ? -g : g;
        gall[ff][t] = g * 0.07957747154594767f;              // 1/(4*pi)
    }
    __syncthreads();

    // Deterministic fixed-order reduction; frame 0 in warp 0, frame 1 in warp 4.
    {
        const int ff = t >> 7;
        const int c  = t & 127;
        if (c < NG) {
            const int pa = c / 5;
            const int pb = c - 5 * pa;
            const int i0 = c_base[pa], na = c_cnt[pa];
            const int j0 = c_base[pb], nb = c_cnt[pb];
            float s = 0.f;
            for (int u = 0; u < na; u++)
                for (int v = 0; v < nb; v++)
                    s += gall[ff][(i0 + u) * 16 + (j0 + v)];
            g_gli[c * NFRM + (bf0 + ff)] = s;    // channel-major
        }
    }
}

// Velocity: channel-major gli -> fully coalesced loads; one thread per output.
__global__ __launch_bounds__(256)
void vel_kernel(float* __restrict__ out)
{
    const int n = B_DIM * (F_DIM - 1);
    int idx = blockIdx.x * blockDim.x + threadIdx.x;
    if (idx >= n) return;
    int b  = idx / (F_DIM - 1);
    int f  = idx - b * (F_DIM - 1);
    int bf = b * F_DIM + f;
    float m = 0.f;
#pragma unroll
    for (int c = 0; c < NG; c++) {
        float a0 = g_gli[c * NFRM + bf];
        float a1 = g_gli[c * NFRM + bf + 1];
        m = fmaxf(m, fabsf(a1 - a0));
    }
    out[idx] = m;
}

extern "C" void kernel_launch(void* const* d_in, const int* in_sizes, int n_in,
                              void* d_out, int out_size)
{
    const float* m1 = (const float*)d_in[0];   // motion1 (32,1024,22,3) f32
    const float* m2 = (const float*)d_in[1];   // motion2 (32,1024,22,3) f32
    float* out = (float*)d_out;                // (32,1023) f32

    gli_kernel<<<NFRM / FPC, 256>>>(m1, m2);

    const int n = B_DIM * (F_DIM - 1);
    vel_kernel<<<(n + 255) / 256, 256>>>(out);
}

// round 16
// speedup vs baseline: 1.6175x; 1.0639x over previous
#include <cuda_runtime.h>
#include <math.h>

// Problem dims
#define B_DIM 32
#define F_DIM 1024
#define NG    25
#define NFRM  (B_DIM * F_DIM)
#define FPC   4                       // frames per CTA

// gli scratch, CHANNEL-MAJOR: g_gli[c * NFRM + bf]  (coalesced vel reads)
__device__ float g_gli[NG * NFRM];

// Segment tables (16 segments across 5 paths)
// paths: [2,5,8,11], [1,4,7,10], [3,6,9,12,15], [14,17,19,21], [13,16,18,20]
__constant__ unsigned char c_ss[16]   = {2,5,8, 1,4,7, 3,6,9,12, 14,17,19, 13,16,18};
__constant__ unsigned char c_se[16]   = {5,8,11, 4,7,10, 6,9,12,15, 17,19,21, 16,18,20};
__constant__ unsigned char c_base[5]  = {0,3,6,10,13};
__constant__ unsigned char c_cnt[5]   = {3,3,4,3,3};

// Branch-free asin, A&S 4.4.46 (abs err <= 2e-8), MUFU-only sqrt:
// asin(x) = sign(x) * ( pi/2 - sqrt(1-|x|) * poly7(|x|) )
__device__ __forceinline__ float fast_asin(float v) {
    float x = fabsf(v);
    float p = fmaf(x, -0.0012624911f,  0.0066700901f);
    p = fmaf(p, x, -0.0170881256f);
    p = fmaf(p, x,  0.0308918810f);
    p = fmaf(p, x, -0.0501743046f);
    p = fmaf(p, x,  0.0889789874f);
    p = fmaf(p, x, -0.2145988016f);
    p = fmaf(p, x,  1.5707963050f);
    float y = 1.0f - x;                 // >= 1e-7 after clip
    float s = y * rsqrtf(y);            // sqrt(y) via MUFU.RSQ, no IEEE slow path
    float r = fmaf(-s, p, 1.57079632679f);
    return copysignf(r, v);
}

// asin( clip( d / sqrt(qa*qb) ) ), zero-norm -> 0 (matches reference where())
__device__ __forceinline__ float edge_term(float d, float qa, float qb) {
    float p = qa * qb;
    float r = rsqrtf(p);
    float v = (p > 0.f) ? d * r : 0.f;
    v = fminf(fmaxf(v, -1.f + 1e-7f), 1.f - 1e-7f);
    return fast_asin(v);
}

__global__ __launch_bounds__(256)
void gli_kernel(const float* __restrict__ m1, const float* __restrict__ m2)
{
    __shared__ float4 J1v[FPC][22];     // motion1 joints, float4-padded
    __shared__ float4 J2v[FPC][22];     // motion2 joints
    __shared__ float4 R12[FPC][16];     // e1_i - s1_i per segment
    __shared__ float4 R34[FPC][16];     // e2_j - s2_j per segment
    __shared__ float  gall[FPC][256];
    __shared__ unsigned char ss[16];

    const int t   = threadIdx.x;
    const int bf0 = blockIdx.x * FPC;

    // Load phase: 64 lanes per frame stage that frame's tables. One barrier.
    {
        const int ff = t >> 6;              // 0..3
        const int u  = t & 63;              // lane within frame group
        const float* base1 = m1 + (bf0 + ff) * 66;
        const float* base2 = m2 + (bf0 + ff) * 66;
        if (u < 22) {
            J1v[ff][u] = make_float4(base1[3*u], base1[3*u+1], base1[3*u+2], 0.f);
        } else if (u < 44) {
            int a = u - 22;
            J2v[ff][a] = make_float4(base2[3*a], base2[3*a+1], base2[3*a+2], 0.f);
        } else if (u < 60) {
            int i = u - 44;
            int s = 3 * (int)c_ss[i], e = 3 * (int)c_se[i];
            R12[ff][i] = make_float4(base1[e]-base1[s], base1[e+1]-base1[s+1],
                                     base1[e+2]-base1[s+2], 0.f);
            R34[ff][i] = make_float4(base2[e]-base2[s], base2[e+1]-base2[s+1],
                                     base2[e+2]-base2[s+2], 0.f);
        }
        if (t < 16) ss[t] = c_ss[t];
    }
    __syncthreads();

    // ---- per-pair Gauss integral for 4 frames, 2-way interleaved (ILP x2) ----
    // P = r13 x r34, Q = r12 x r13, R = r12 x r34
    // f0 = P, f1 = Q+R, f2 = R-P, f3 = -Q, sign = -(R . r13)
    const int i  = t >> 4;              // motion1 segment
    const int j  = t & 15;              // motion2 segment
    const int si = (int)ss[i];
    const int sj = (int)ss[j];

#pragma unroll 2
    for (int ff = 0; ff < FPC; ff++) {
        float4 p1 = J1v[ff][si];        // s1
        float4 p2 = J2v[ff][sj];        // s2
        float4 A  = R12[ff][i];         // r12
        float4 B  = R34[ff][j];         // r34

        float rx = p2.x - p1.x, ry = p2.y - p1.y, rz = p2.z - p1.z;   // r13

        float Px = ry*B.z - rz*B.y, Py = rz*B.x - rx*B.z, Pz = rx*B.y - ry*B.x;
        float Qx = A.y*rz - A.z*ry, Qy = A.z*rx - A.x*rz, Qz = A.x*ry - A.y*rx;
        float Rx = A.y*B.z - A.z*B.y, Ry = A.z*B.x - A.x*B.z, Rz = A.x*B.y - A.y*B.x;

        float f1x = Qx + Rx, f1y = Qy + Ry, f1z = Qz + Rz;   // f1
        float f2x = Rx - Px, f2y = Ry - Py, f2z = Rz - Pz;   // f2

        float q0 = Px*Px + Py*Py + Pz*Pz;
        float q1 = f1x*f1x + f1y*f1y + f1z*f1z;
        float q2 = f2x*f2x + f2y*f2y + f2z*f2z;
        float q3 = Qx*Qx + Qy*Qy + Qz*Qz;

        float d01 = Px*f1x + Py*f1y + Pz*f1z;                // f0.f1
        float d12 = f1x*f2x + f1y*f2y + f1z*f2z;             // f1.f2
        float d23 = f2x*Qx + f2y*Qy + f2z*Qz;                // -(f2.f3)
        float d30 = Px*Qx + Py*Qy + Pz*Qz;                   // -(f3.f0)

        float g = edge_term(d01, q0, q1)
                + edge_term(d12, q1, q2)
                - edge_term(d23, q2, q3)
                - edge_term(d30, q3, q0);

        float sgn = -(Rx*rx + Ry*ry + Rz*rz);                // dot(cross(r34,r12), r13)
        g = (sgn <= 0.f) ? -g : g;
        gall[ff][t] = g * 0.07957747154594767f;              // 1/(4*pi)
    }
    __syncthreads();

    // Deterministic fixed-order reduction; 4 frames reduced concurrently
    // (frame ff handled by lanes [64*ff, 64*ff+25)).
    {
        const int ff = t >> 6;
        const int c  = t & 63;
        if (c < NG) {
            const int pa = c / 5;
            const int pb = c - 5 * pa;
            const int i0 = c_base[pa], na = c_cnt[pa];
            const int j0 = c_base[pb], nb = c_cnt[pb];
            float s = 0.f;
            for (int u = 0; u < na; u++)
                for (int v = 0; v < nb; v++)
                    s += gall[ff][(i0 + u) * 16 + (j0 + v)];
            g_gli[c * NFRM + (bf0 + ff)] = s;    // channel-major
        }
    }
}

// Velocity: 2 threads per output, channel-major coalesced loads, butterfly max.
__global__ __launch_bounds__(256)
void vel_kernel(float* __restrict__ out)
{
    const int n = B_DIM * (F_DIM - 1);
    int gid  = blockIdx.x * blockDim.x + threadIdx.x;
    int idx  = gid >> 1;
    int h    = gid & 1;
    if (idx >= n) return;
    int b  = idx / (F_DIM - 1);
    int f  = idx - b * (F_DIM - 1);
    int bf = b * F_DIM + f;
    float m = 0.f;
#pragma unroll
    for (int c = h; c < NG; c += 2) {
        float a0 = g_gli[c * NFRM + bf];
        float a1 = g_gli[c * NFRM + bf + 1];
        m = fmaxf(m, fabsf(a1 - a0));
    }
    m = fmaxf(m, __shfl_xor_sync(0xffffffffu, m, 1));
    if (h == 0) out[idx] = m;
}

extern "C" void kernel_launch(void* const* d_in, const int* in_sizes, int n_in,
                              void* d_out, int out_size)
{
    const float* m1 = (const float*)d_in[0];   // motion1 (32,1024,22,3) f32
    const float* m2 = (const float*)d_in[1];   // motion2 (32,1024,22,3) f32
    float* out = (float*)d_out;                // (32,1023) f32

    gli_kernel<<<NFRM / FPC, 256>>>(m1, m2);

    const int nthreads = B_DIM * (F_DIM - 1) * 2;
    vel_kernel<<<(nthreads + 255) / 256, 256>>>(out);
}